// round 13
// baseline (speedup 1.0000x reference)
#include <cuda_runtime.h>
#include <cuda_fp16.h>

// Problem constants (from reference)
#define K_GENES 20000
#define N_GO    5000
#define BATCH   4096
#define CAP     128            // per-column entry capacity (Poisson(16); max ~50)
#define JT      16             // columns per spmm block
#define BT      256            // batch elems per spmm block
#define CHUNK   512            // batch rows per chunk (staging 20MB x2 buffers, L2-resident)
#define NCHUNK  (BATCH / CHUNK)              // 8

#define CT      ((N_GO + JT - 1) / JT)       // 313 column tiles
#define NSP     (CT * (CHUNK / BT))          // 626 spmm blocks per chunk
#define GT      313                          // gene tiles: ceil(20000/64)
#define NTR     (GT * (CHUNK / 64))          // 2504 transpose blocks per chunk
#define NB_BUILD 4736                        // build role blocks in fused kernel A

// Scratch in device globals. Double-buffered staging: [buf][gene][CHUNK] fp16.
__device__ __half g_stage[2 * (size_t)K_GENES * CHUNK];
__device__ int    g_cnt[N_GO];
__device__ int    g_ei [(size_t)N_GO * CAP];       // unsorted gene idx (build out)
__device__ float  g_ev [(size_t)N_GO * CAP];       // unsorted values   (build out)
__device__ int2   g_ent[(size_t)N_GO * (CAP + 2)]; // sorted packed {byteoff, w} (+2 pad)

// Shared-memory union: transpose tile OR spmm working set (never both in a block)
union SmemU {
    struct { float tile[64][65]; } tr;                 // 16.6 KB
    struct {
        int2  ent[8][CAP + 2];                         // 8.3 KB
        float sout[BT][JT + 1];                        // 17.4 KB
    } sp;                                              // 25.7 KB
};

// ---------------------------------------------------------------------------
__global__ void zero_cnt_kernel() {
    int t = blockIdx.x * blockDim.x + threadIdx.x;
    if (t < N_GO) g_cnt[t] = 0;
}

// ---------------------------------------------------------------------------
// build role: scan mask (evict-first stream), append (gene, w*m) per column
__device__ __forceinline__ void build_role(const float* __restrict__ w,
                                           const float* __restrict__ m,
                                           int vblock) {
    const float4* m4 = (const float4*)m;
    const long total4 = (long)K_GENES * N_GO / 4;
    long stride = (long)NB_BUILD * 256;
    for (long idx = (long)vblock * 256 + threadIdx.x; idx < total4; idx += stride) {
        float4 mv = __ldcs(m4 + idx);
        if (mv.x != 0.f || mv.y != 0.f || mv.z != 0.f || mv.w != 0.f) {
            float lane[4] = {mv.x, mv.y, mv.z, mv.w};
            long base = idx * 4;
            #pragma unroll
            for (int c = 0; c < 4; c++) {
                if (lane[c] != 0.f) {
                    long lin = base + c;
                    int i = (int)(lin / N_GO);
                    int j = (int)(lin - (long)i * N_GO);
                    float wv = __ldg(w + lin) * lane[c];
                    int pos = atomicAdd(&g_cnt[j], 1);
                    if (pos < CAP) {
                        g_ei[(size_t)j * CAP + pos] = i;
                        g_ev[(size_t)j * CAP + pos] = wv;
                    }
                }
            }
        }
    }
}

// ---------------------------------------------------------------------------
// transpose role: one 64-gene x 64-batch tile of chunk -> staging buf
__device__ __forceinline__ void transpose_role(SmemU* s, const float* __restrict__ in,
                                               int chunk, int buf, int vblock) {
    __half* stg = g_stage + (size_t)buf * K_GENES * CHUNK;
    int t  = threadIdx.x;
    int c0 = (vblock % GT) * 64;             // gene base
    int rl = (vblock / GT) * 64;             // batch base within chunk
    int r0 = chunk * CHUNK + rl;             // global batch base

    int fx = t & 15;
    int rr = t >> 4;
    bool cok = (c0 + 4 * fx) < K_GENES;
    #pragma unroll
    for (int p = 0; p < 4; p++) {
        int r = rr + 16 * p;
        if (cok) {
            float4 v = __ldcs((const float4*)(in + (size_t)(r0 + r) * K_GENES + c0 + 4 * fx));
            s->tr.tile[r][4 * fx + 0] = v.x;
            s->tr.tile[r][4 * fx + 1] = v.y;
            s->tr.tile[r][4 * fx + 2] = v.z;
            s->tr.tile[r][4 * fx + 3] = v.w;
        }
    }
    __syncthreads();

    int u  = t & 7;
    int gl = t >> 3;
    #pragma unroll
    for (int p = 0; p < 2; p++) {
        int g = gl + 32 * p;
        if (c0 + g < K_GENES) {
            __half2 h0 = __floats2half2_rn(s->tr.tile[8 * u + 0][g], s->tr.tile[8 * u + 1][g]);
            __half2 h1 = __floats2half2_rn(s->tr.tile[8 * u + 2][g], s->tr.tile[8 * u + 3][g]);
            __half2 h2 = __floats2half2_rn(s->tr.tile[8 * u + 4][g], s->tr.tile[8 * u + 5][g]);
            __half2 h3 = __floats2half2_rn(s->tr.tile[8 * u + 6][g], s->tr.tile[8 * u + 7][g]);
            uint4 o;
            o.x = *(unsigned*)&h0; o.y = *(unsigned*)&h1;
            o.z = *(unsigned*)&h2; o.w = *(unsigned*)&h3;
            *(uint4*)&stg[(size_t)(c0 + g) * CHUNK + rl + 8 * u] = o;
        }
    }
}

// ---------------------------------------------------------------------------
// spmm role: (16 cols x 256 batch) tile of chunk from L2-resident staging.
// Warp w owns 2 columns. Packed int2 entries (pre-multiplied byte offset),
// depth-2 LDG.128 prefetch.
__device__ __forceinline__ void spmm_role(SmemU* s, float* __restrict__ out,
                                          int chunk, int buf, int vblock) {
    const char* stg = (const char*)(g_stage + (size_t)buf * K_GENES * CHUNK);
    int ct    = vblock % CT;                 // column tile
    int bc    = vblock / CT;                 // batch sub-chunk
    int w     = threadIdx.x >> 5;
    int lane  = threadIdx.x & 31;
    int bl    = bc * BT;                     // batch base within chunk
    int b0    = chunk * CHUNK + bl;          // global batch base
    int jbase = ct * JT + w * 2;

    #pragma unroll
    for (int cc = 0; cc < 2; cc++) {
        int j = jbase + cc;
        int n = 0;
        if (j < N_GO) n = min(g_cnt[j], CAP);
        size_t lbase = (size_t)j * (CAP + 2);

        for (int e = lane; e < n + 2 && j < N_GO; e += 32) {
            s->sp.ent[w][e] = g_ent[lbase + e];
        }
        __syncwarp();

        float acc[8];
        #pragma unroll
        for (int q = 0; q < 8; q++) acc[q] = 0.f;

        const char* xb = stg + bl * 2 + lane * 16;
        if (n > 0) {
            int2 e0 = s->sp.ent[w][0];
            int2 e1 = s->sp.ent[w][1];
            uint4 u0 = __ldg((const uint4*)(xb + e0.x));
            uint4 u1 = __ldg((const uint4*)(xb + e1.x));
            for (int e = 0; e < n; e++) {
                uint4 cur = u0;
                float v = __int_as_float(e0.y);
                u0 = u1;
                e0 = e1;
                e1 = s->sp.ent[w][e + 2];
                u1 = __ldg((const uint4*)(xb + e1.x));
                float2 f0 = __half22float2(*(__half2*)&cur.x);
                float2 f1 = __half22float2(*(__half2*)&cur.y);
                float2 f2 = __half22float2(*(__half2*)&cur.z);
                float2 f3 = __half22float2(*(__half2*)&cur.w);
                acc[0] = fmaf(f0.x, v, acc[0]);
                acc[1] = fmaf(f0.y, v, acc[1]);
                acc[2] = fmaf(f1.x, v, acc[2]);
                acc[3] = fmaf(f1.y, v, acc[3]);
                acc[4] = fmaf(f2.x, v, acc[4]);
                acc[5] = fmaf(f2.y, v, acc[5]);
                acc[6] = fmaf(f3.x, v, acc[6]);
                acc[7] = fmaf(f3.y, v, acc[7]);
            }
        }
        __syncwarp();

        #pragma unroll
        for (int q = 0; q < 8; q++) {
            s->sp.sout[lane * 8 + q][w * 2 + cc] = acc[q];
        }
    }
    __syncthreads();

    // coalesced evict-first write: 64B per row segment out[b, j0..j0+15]
    int col = threadIdx.x & 15;
    int j   = ct * JT + col;
    if (j < N_GO) {
        #pragma unroll
        for (int r = threadIdx.x >> 4; r < BT; r += 16) {
            __stcs(&out[(size_t)(b0 + r) * N_GO + j], s->sp.sout[r][col]);
        }
    }
}

// ---------------------------------------------------------------------------
// Fused A: build entries (all) + transpose chunk 0 into buffer 0
// launch_bounds(256, 7): 36-reg budget -> no spills (natural usage ~34)
__global__ void __launch_bounds__(256, 7)
fused_build_transpose_kernel(const float* __restrict__ x,
                             const float* __restrict__ w,
                             const float* __restrict__ m) {
    __shared__ SmemU s;
    if (blockIdx.x < NB_BUILD) {
        build_role(w, m, blockIdx.x);
    } else {
        transpose_role(&s, x, 0, 0, blockIdx.x - NB_BUILD);
    }
}

// ---------------------------------------------------------------------------
// Fused B: spmm chunk c from buf (c&1) + (optionally) transpose chunk c+1
// into the other buffer. Kernel boundary orders transpose(c) before spmm(c).
__global__ void __launch_bounds__(256, 7)
fused_spmm_transpose_kernel(float* __restrict__ out,
                            const float* __restrict__ x,
                            int chunk, int do_transpose) {
    __shared__ SmemU s;
    int buf = chunk & 1;
    if (blockIdx.x < NSP) {
        spmm_role(&s, out, chunk, buf, blockIdx.x);
    } else if (do_transpose) {
        transpose_role(&s, x, chunk + 1, buf ^ 1, blockIdx.x - NSP);
    }
}

// ---------------------------------------------------------------------------
// sort each column's entry list by gene id once (deterministic FP order),
// emit packed {byte_offset = gene*CHUNK*2, weight} entries + 2 zero-wt tails.
__global__ void sort_entries_kernel() {
    __shared__ int   s_i[8][CAP];
    __shared__ float s_v[8][CAP];
    int w    = threadIdx.x >> 5;
    int lane = threadIdx.x & 31;
    int j    = blockIdx.x * 8 + w;
    if (j >= N_GO) return;
    int n = min(g_cnt[j], CAP);
    size_t obase = (size_t)j * (CAP + 2);

    for (int e = lane; e < n; e += 32) {
        s_i[w][e] = g_ei[(size_t)j * CAP + e];
        s_v[w][e] = g_ev[(size_t)j * CAP + e];
    }
    __syncwarp();
    for (int p = 0; p < n; p++) {
        for (int k = (p & 1) + 2 * lane; k + 1 < n; k += 64) {
            if (s_i[w][k] > s_i[w][k + 1]) {
                int   ti = s_i[w][k]; s_i[w][k] = s_i[w][k + 1]; s_i[w][k + 1] = ti;
                float tv = s_v[w][k]; s_v[w][k] = s_v[w][k + 1]; s_v[w][k + 1] = tv;
            }
        }
        __syncwarp();
    }
    for (int e = lane; e < n; e += 32) {
        g_ent[obase + e] = make_int2(s_i[w][e] * (CHUNK * 2), __float_as_int(s_v[w][e]));
    }
    if (lane < 2) {
        int last = (n > 0) ? s_i[w][n - 1] * (CHUNK * 2) : 0;
        g_ent[obase + n + lane] = make_int2(last, 0);
    }
}

// ---------------------------------------------------------------------------
extern "C" void kernel_launch(void* const* d_in, const int* in_sizes, int n_in,
                              void* d_out, int out_size) {
    const float* x = (const float*)d_in[0];   // [4096, 20000]
    const float* w = (const float*)d_in[1];   // [20000, 5000]
    const float* m = (const float*)d_in[2];   // [20000, 5000]
    float* out = (float*)d_out;               // [4096, 5000]

    zero_cnt_kernel<<<(N_GO + 255) / 256, 256>>>();

    // A: build (all entries) + transpose chunk 0 into buf 0
    fused_build_transpose_kernel<<<NB_BUILD + NTR, 256>>>(x, w, m);

    sort_entries_kernel<<<(N_GO + 7) / 8, 256>>>();

    // B: spmm chunk c overlapped with transpose chunk c+1 (double-buffered)
    for (int c = 0; c < NCHUNK; c++) {
        int do_tr = (c + 1 < NCHUNK);
        int grid  = NSP + (do_tr ? NTR : 0);
        fused_spmm_transpose_kernel<<<grid, 256>>>(out, x, c, do_tr);
    }
}

// round 15
// speedup vs baseline: 1.3650x; 1.3650x over previous
#include <cuda_runtime.h>
#include <cuda_fp16.h>

// Problem constants (from reference)
#define K_GENES 20000
#define N_GO    5000
#define BATCH   4096
#define CAP     128            // per-column entry capacity (Poisson(16); max ~50)
#define JT      16             // columns per spmm block
#define BT      256            // batch elems per spmm block
#define CHUNK   512            // batch rows per chunk (staging 20MB x2 buffers, L2-resident)
#define NCHUNK  (BATCH / CHUNK)              // 8

#define CT      ((N_GO + JT - 1) / JT)       // 313 column tiles
#define NSP     (CT * (CHUNK / BT))          // 626 spmm blocks per chunk
#define GT      313                          // gene tiles: ceil(20000/64)
#define NTR     (GT * (CHUNK / 64))          // 2504 transpose blocks per chunk
#define NB_BUILD 4736                        // build role blocks in fused kernel A

// Scratch in device globals. Double-buffered staging: [buf][gene][CHUNK] fp16.
__device__ __half g_stage[2 * (size_t)K_GENES * CHUNK];
__device__ int    g_cnt[N_GO];
__device__ int    g_ei [(size_t)N_GO * (CAP + 2)]; // gene index per entry (padded)
__device__ float  g_ev [(size_t)N_GO * (CAP + 2)]; // weight*mask value (padded)

// Shared-memory union: transpose tile OR spmm working set (never both in a block)
union SmemU {
    struct { float tile[64][65]; } tr;                 // 16.6 KB
    struct {
        int   ei[8][CAP + 2];                          // 4.2 KB
        float ev[8][CAP + 2];                          // 4.2 KB
        float sout[BT][JT + 1];                        // 17.4 KB
    } sp;                                              // 25.7 KB
};

// ---------------------------------------------------------------------------
// build role: scan mask (evict-first stream), append (gene, w*m) per column
__device__ __forceinline__ void build_role(const float* __restrict__ w,
                                           const float* __restrict__ m,
                                           int vblock) {
    const float4* m4 = (const float4*)m;
    const long total4 = (long)K_GENES * N_GO / 4;
    long stride = (long)NB_BUILD * 256;
    for (long idx = (long)vblock * 256 + threadIdx.x; idx < total4; idx += stride) {
        float4 mv = __ldcs(m4 + idx);
        if (mv.x != 0.f || mv.y != 0.f || mv.z != 0.f || mv.w != 0.f) {
            float lane[4] = {mv.x, mv.y, mv.z, mv.w};
            long base = idx * 4;
            #pragma unroll
            for (int c = 0; c < 4; c++) {
                if (lane[c] != 0.f) {
                    long lin = base + c;
                    int i = (int)(lin / N_GO);
                    int j = (int)(lin - (long)i * N_GO);
                    float wv = __ldg(w + lin) * lane[c];
                    int pos = atomicAdd(&g_cnt[j], 1);
                    if (pos < CAP) {
                        g_ei[(size_t)j * (CAP + 2) + pos] = i;
                        g_ev[(size_t)j * (CAP + 2) + pos] = wv;
                    }
                }
            }
        }
    }
}

// ---------------------------------------------------------------------------
// transpose role: one 64-gene x 64-batch tile of chunk -> staging buf
__device__ __forceinline__ void transpose_role(SmemU* s, const float* __restrict__ in,
                                               int chunk, int buf, int vblock) {
    __half* stg = g_stage + (size_t)buf * K_GENES * CHUNK;
    int t  = threadIdx.x;
    int c0 = (vblock % GT) * 64;             // gene base
    int rl = (vblock / GT) * 64;             // batch base within chunk
    int r0 = chunk * CHUNK + rl;             // global batch base

    int fx = t & 15;
    int rr = t >> 4;
    bool cok = (c0 + 4 * fx) < K_GENES;
    #pragma unroll
    for (int p = 0; p < 4; p++) {
        int r = rr + 16 * p;
        if (cok) {
            float4 v = __ldcs((const float4*)(in + (size_t)(r0 + r) * K_GENES + c0 + 4 * fx));
            s->tr.tile[r][4 * fx + 0] = v.x;
            s->tr.tile[r][4 * fx + 1] = v.y;
            s->tr.tile[r][4 * fx + 2] = v.z;
            s->tr.tile[r][4 * fx + 3] = v.w;
        }
    }
    __syncthreads();

    int u  = t & 7;
    int gl = t >> 3;
    #pragma unroll
    for (int p = 0; p < 2; p++) {
        int g = gl + 32 * p;
        if (c0 + g < K_GENES) {
            __half2 h0 = __floats2half2_rn(s->tr.tile[8 * u + 0][g], s->tr.tile[8 * u + 1][g]);
            __half2 h1 = __floats2half2_rn(s->tr.tile[8 * u + 2][g], s->tr.tile[8 * u + 3][g]);
            __half2 h2 = __floats2half2_rn(s->tr.tile[8 * u + 4][g], s->tr.tile[8 * u + 5][g]);
            __half2 h3 = __floats2half2_rn(s->tr.tile[8 * u + 6][g], s->tr.tile[8 * u + 7][g]);
            uint4 o;
            o.x = *(unsigned*)&h0; o.y = *(unsigned*)&h1;
            o.z = *(unsigned*)&h2; o.w = *(unsigned*)&h3;
            *(uint4*)&stg[(size_t)(c0 + g) * CHUNK + rl + 8 * u] = o;
        }
    }
}

// ---------------------------------------------------------------------------
// spmm role: (16 cols x 256 batch) tile of chunk from L2-resident staging.
// Warp w owns 2 columns. Separate int/float entry arrays + size_t IMAD
// addressing (measured-fast form), depth-2 LDG.128 prefetch.
__device__ __forceinline__ void spmm_role(SmemU* s, float* __restrict__ out,
                                          int chunk, int buf, int vblock) {
    const __half* stg = g_stage + (size_t)buf * K_GENES * CHUNK;
    int ct    = vblock % CT;                 // column tile
    int bc    = vblock / CT;                 // batch sub-chunk
    int w     = threadIdx.x >> 5;
    int lane  = threadIdx.x & 31;
    int bl    = bc * BT;                     // batch base within chunk
    int b0    = chunk * CHUNK + bl;          // global batch base
    int jbase = ct * JT + w * 2;

    #pragma unroll
    for (int cc = 0; cc < 2; cc++) {
        int j = jbase + cc;
        int n = 0;
        if (j < N_GO) n = min(g_cnt[j], CAP);
        size_t lbase = (size_t)j * (CAP + 2);

        for (int e = lane; e < n + 2 && j < N_GO; e += 32) {
            s->sp.ei[w][e] = g_ei[lbase + e];
            s->sp.ev[w][e] = g_ev[lbase + e];
        }
        __syncwarp();

        float acc[8];
        #pragma unroll
        for (int q = 0; q < 8; q++) acc[q] = 0.f;

        const __half* xb = stg + bl + lane * 8;
        if (n > 0) {
            uint4 u0 = __ldg((const uint4*)(xb + (size_t)s->sp.ei[w][0] * CHUNK));
            uint4 u1 = __ldg((const uint4*)(xb + (size_t)s->sp.ei[w][1] * CHUNK));
            for (int e = 0; e < n; e++) {
                uint4 cur = u0;
                u0 = u1;
                u1 = __ldg((const uint4*)(xb + (size_t)s->sp.ei[w][e + 2] * CHUNK));
                float v = s->sp.ev[w][e];
                float2 f0 = __half22float2(*(__half2*)&cur.x);
                float2 f1 = __half22float2(*(__half2*)&cur.y);
                float2 f2 = __half22float2(*(__half2*)&cur.z);
                float2 f3 = __half22float2(*(__half2*)&cur.w);
                acc[0] = fmaf(f0.x, v, acc[0]);
                acc[1] = fmaf(f0.y, v, acc[1]);
                acc[2] = fmaf(f1.x, v, acc[2]);
                acc[3] = fmaf(f1.y, v, acc[3]);
                acc[4] = fmaf(f2.x, v, acc[4]);
                acc[5] = fmaf(f2.y, v, acc[5]);
                acc[6] = fmaf(f3.x, v, acc[6]);
                acc[7] = fmaf(f3.y, v, acc[7]);
            }
        }
        __syncwarp();

        #pragma unroll
        for (int q = 0; q < 8; q++) {
            s->sp.sout[lane * 8 + q][w * 2 + cc] = acc[q];
        }
    }
    __syncthreads();

    // coalesced evict-first write: 64B per row segment out[b, j0..j0+15]
    int col = threadIdx.x & 15;
    int j   = ct * JT + col;
    if (j < N_GO) {
        #pragma unroll
        for (int r = threadIdx.x >> 4; r < BT; r += 16) {
            __stcs(&out[(size_t)(b0 + r) * N_GO + j], s->sp.sout[r][col]);
        }
    }
}

// ---------------------------------------------------------------------------
// Fused A: build entries (all) + transpose chunk 0 into buffer 0
__global__ void fused_build_transpose_kernel(const float* __restrict__ x,
                                             const float* __restrict__ w,
                                             const float* __restrict__ m) {
    __shared__ SmemU s;
    if (blockIdx.x < NB_BUILD) {
        build_role(w, m, blockIdx.x);
    } else {
        transpose_role(&s, x, 0, 0, blockIdx.x - NB_BUILD);
    }
}

// ---------------------------------------------------------------------------
// Fused B: spmm chunk c from buf (c&1) + (optionally) transpose chunk c+1
// into the other buffer. Kernel boundary orders transpose(c) before spmm(c).
__global__ void fused_spmm_transpose_kernel(float* __restrict__ out,
                                            const float* __restrict__ x,
                                            int chunk, int do_transpose) {
    __shared__ SmemU s;
    int buf = chunk & 1;
    if (blockIdx.x < NSP) {
        spmm_role(&s, out, chunk, buf, blockIdx.x);
    } else if (do_transpose) {
        transpose_role(&s, x, chunk + 1, buf ^ 1, blockIdx.x - NSP);
    }
}

// ---------------------------------------------------------------------------
// sort each column's entry list by gene id once (deterministic FP order),
// then write 2 duplicate zero-weight tail entries for the spmm prefetch.
__global__ void sort_entries_kernel() {
    __shared__ int   s_i[8][CAP];
    __shared__ float s_v[8][CAP];
    int w    = threadIdx.x >> 5;
    int lane = threadIdx.x & 31;
    int j    = blockIdx.x * 8 + w;
    if (j >= N_GO) return;
    int n = min(g_cnt[j], CAP);
    size_t base = (size_t)j * (CAP + 2);

    for (int e = lane; e < n; e += 32) {
        s_i[w][e] = g_ei[base + e];
        s_v[w][e] = g_ev[base + e];
    }
    __syncwarp();
    for (int p = 0; p < n; p++) {
        for (int k = (p & 1) + 2 * lane; k + 1 < n; k += 64) {
            if (s_i[w][k] > s_i[w][k + 1]) {
                int   ti = s_i[w][k]; s_i[w][k] = s_i[w][k + 1]; s_i[w][k + 1] = ti;
                float tv = s_v[w][k]; s_v[w][k] = s_v[w][k + 1]; s_v[w][k + 1] = tv;
            }
        }
        __syncwarp();
    }
    for (int e = lane; e < n; e += 32) {
        g_ei[base + e] = s_i[w][e];
        g_ev[base + e] = s_v[w][e];
    }
    if (lane < 2) {
        int last = (n > 0) ? s_i[w][n - 1] : 0;
        g_ei[base + n + lane] = last;
        g_ev[base + n + lane] = 0.f;
    }
}

// ---------------------------------------------------------------------------
extern "C" void kernel_launch(void* const* d_in, const int* in_sizes, int n_in,
                              void* d_out, int out_size) {
    const float* x = (const float*)d_in[0];   // [4096, 20000]
    const float* w = (const float*)d_in[1];   // [20000, 5000]
    const float* m = (const float*)d_in[2];   // [20000, 5000]
    float* out = (float*)d_out;               // [4096, 5000]

    // zero per-column counters via memset node (graph-capturable, no launch)
    void* cntp = nullptr;
    cudaGetSymbolAddress(&cntp, g_cnt);
    cudaMemsetAsync(cntp, 0, N_GO * sizeof(int));

    // A: build (all entries) + transpose chunk 0 into buf 0
    fused_build_transpose_kernel<<<NB_BUILD + NTR, 256>>>(x, w, m);

    sort_entries_kernel<<<(N_GO + 7) / 8, 256>>>();

    // B: spmm chunk c overlapped with transpose chunk c+1 (double-buffered)
    for (int c = 0; c < NCHUNK; c++) {
        int do_tr = (c + 1 < NCHUNK);
        int grid  = NSP + (do_tr ? NTR : 0);
        fused_spmm_transpose_kernel<<<grid, 256>>>(out, x, c, do_tr);
    }
}

// round 16
// speedup vs baseline: 1.3906x; 1.0188x over previous
#include <cuda_runtime.h>
#include <cuda_fp16.h>

// Problem constants (from reference)
#define K_GENES 20000
#define N_GO    5000
#define BATCH   4096
#define CAP     128            // per-column entry capacity (Poisson(16); max ~50)
#define PAD     4              // prefetch-depth padding entries
#define JT      16             // columns per spmm block
#define BT      256            // batch elems per spmm block
#define CHUNK   512            // batch rows per chunk (staging 20MB x2 buffers, L2-resident)
#define NCHUNK  (BATCH / CHUNK)              // 8

#define CT      ((N_GO + JT - 1) / JT)       // 313 column tiles
#define NSP     (CT * (CHUNK / BT))          // 626 spmm blocks per chunk
#define GT      313                          // gene tiles: ceil(20000/64)
#define NTR     (GT * (CHUNK / 64))          // 2504 transpose blocks per chunk
#define NB_BUILD 4736                        // build role blocks in fused kernel A

// Scratch in device globals. Double-buffered staging: [buf][gene][CHUNK] fp16.
__device__ __half g_stage[2 * (size_t)K_GENES * CHUNK];
__device__ int    g_cnt[N_GO];
__device__ int    g_ei [(size_t)N_GO * (CAP + PAD)]; // gene index per entry (padded)
__device__ float  g_ev [(size_t)N_GO * (CAP + PAD)]; // weight*mask value (padded)

// Shared-memory union: transpose tile OR spmm working set (never both in a block)
union SmemU {
    struct { float tile[64][65]; } tr;                 // 16.6 KB
    struct {
        int   ei[8][CAP + PAD];                        // 4.2 KB
        float ev[8][CAP + PAD];                        // 4.2 KB
        float sout[BT][JT + 1];                        // 17.4 KB
    } sp;                                              // 25.8 KB
};

// ---------------------------------------------------------------------------
// build role: scan mask (evict-first stream), append (gene, w*m) per column
__device__ __forceinline__ void build_role(const float* __restrict__ w,
                                           const float* __restrict__ m,
                                           int vblock) {
    const float4* m4 = (const float4*)m;
    const long total4 = (long)K_GENES * N_GO / 4;
    long stride = (long)NB_BUILD * 256;
    for (long idx = (long)vblock * 256 + threadIdx.x; idx < total4; idx += stride) {
        float4 mv = __ldcs(m4 + idx);
        if (mv.x != 0.f || mv.y != 0.f || mv.z != 0.f || mv.w != 0.f) {
            float lane[4] = {mv.x, mv.y, mv.z, mv.w};
            long base = idx * 4;
            #pragma unroll
            for (int c = 0; c < 4; c++) {
                if (lane[c] != 0.f) {
                    long lin = base + c;
                    int i = (int)(lin / N_GO);
                    int j = (int)(lin - (long)i * N_GO);
                    float wv = __ldg(w + lin) * lane[c];
                    int pos = atomicAdd(&g_cnt[j], 1);
                    if (pos < CAP) {
                        g_ei[(size_t)j * (CAP + PAD) + pos] = i;
                        g_ev[(size_t)j * (CAP + PAD) + pos] = wv;
                    }
                }
            }
        }
    }
}

// ---------------------------------------------------------------------------
// transpose role: one 64-gene x 64-batch tile of chunk -> staging buf
__device__ __forceinline__ void transpose_role(SmemU* s, const float* __restrict__ in,
                                               int chunk, int buf, int vblock) {
    __half* stg = g_stage + (size_t)buf * K_GENES * CHUNK;
    int t  = threadIdx.x;
    int c0 = (vblock % GT) * 64;             // gene base
    int rl = (vblock / GT) * 64;             // batch base within chunk
    int r0 = chunk * CHUNK + rl;             // global batch base

    int fx = t & 15;
    int rr = t >> 4;
    bool cok = (c0 + 4 * fx) < K_GENES;
    #pragma unroll
    for (int p = 0; p < 4; p++) {
        int r = rr + 16 * p;
        if (cok) {
            float4 v = __ldcs((const float4*)(in + (size_t)(r0 + r) * K_GENES + c0 + 4 * fx));
            s->tr.tile[r][4 * fx + 0] = v.x;
            s->tr.tile[r][4 * fx + 1] = v.y;
            s->tr.tile[r][4 * fx + 2] = v.z;
            s->tr.tile[r][4 * fx + 3] = v.w;
        }
    }
    __syncthreads();

    int u  = t & 7;
    int gl = t >> 3;
    #pragma unroll
    for (int p = 0; p < 2; p++) {
        int g = gl + 32 * p;
        if (c0 + g < K_GENES) {
            __half2 h0 = __floats2half2_rn(s->tr.tile[8 * u + 0][g], s->tr.tile[8 * u + 1][g]);
            __half2 h1 = __floats2half2_rn(s->tr.tile[8 * u + 2][g], s->tr.tile[8 * u + 3][g]);
            __half2 h2 = __floats2half2_rn(s->tr.tile[8 * u + 4][g], s->tr.tile[8 * u + 5][g]);
            __half2 h3 = __floats2half2_rn(s->tr.tile[8 * u + 6][g], s->tr.tile[8 * u + 7][g]);
            uint4 o;
            o.x = *(unsigned*)&h0; o.y = *(unsigned*)&h1;
            o.z = *(unsigned*)&h2; o.w = *(unsigned*)&h3;
            *(uint4*)&stg[(size_t)(c0 + g) * CHUNK + rl + 8 * u] = o;
        }
    }
}

// ---------------------------------------------------------------------------
// spmm role: (16 cols x 256 batch) tile of chunk from L2-resident staging.
// Warp w owns 2 columns. Depth-4 LDG.128 prefetch (lists padded with 4
// duplicate zero-weight tail entries) -> MLP=4 per warp.
__device__ __forceinline__ void spmm_role(SmemU* s, float* __restrict__ out,
                                          int chunk, int buf, int vblock) {
    const __half* stg = g_stage + (size_t)buf * K_GENES * CHUNK;
    int ct    = vblock % CT;                 // column tile
    int bc    = vblock / CT;                 // batch sub-chunk
    int w     = threadIdx.x >> 5;
    int lane  = threadIdx.x & 31;
    int bl    = bc * BT;                     // batch base within chunk
    int b0    = chunk * CHUNK + bl;          // global batch base
    int jbase = ct * JT + w * 2;

    #pragma unroll
    for (int cc = 0; cc < 2; cc++) {
        int j = jbase + cc;
        int n = 0;
        if (j < N_GO) n = min(g_cnt[j], CAP);
        size_t lbase = (size_t)j * (CAP + PAD);

        for (int e = lane; e < n + PAD && j < N_GO; e += 32) {
            s->sp.ei[w][e] = g_ei[lbase + e];
            s->sp.ev[w][e] = g_ev[lbase + e];
        }
        __syncwarp();

        float acc[8];
        #pragma unroll
        for (int q = 0; q < 8; q++) acc[q] = 0.f;

        const __half* xb = stg + bl + lane * 8;
        if (n > 0) {
            uint4 u0 = __ldg((const uint4*)(xb + (size_t)s->sp.ei[w][0] * CHUNK));
            uint4 u1 = __ldg((const uint4*)(xb + (size_t)s->sp.ei[w][1] * CHUNK));
            uint4 u2 = __ldg((const uint4*)(xb + (size_t)s->sp.ei[w][2] * CHUNK));
            uint4 u3 = __ldg((const uint4*)(xb + (size_t)s->sp.ei[w][3] * CHUNK));
            for (int e = 0; e < n; e++) {
                uint4 cur = u0;
                u0 = u1; u1 = u2; u2 = u3;
                u3 = __ldg((const uint4*)(xb + (size_t)s->sp.ei[w][e + 4] * CHUNK));
                float v = s->sp.ev[w][e];
                float2 f0 = __half22float2(*(__half2*)&cur.x);
                float2 f1 = __half22float2(*(__half2*)&cur.y);
                float2 f2 = __half22float2(*(__half2*)&cur.z);
                float2 f3 = __half22float2(*(__half2*)&cur.w);
                acc[0] = fmaf(f0.x, v, acc[0]);
                acc[1] = fmaf(f0.y, v, acc[1]);
                acc[2] = fmaf(f1.x, v, acc[2]);
                acc[3] = fmaf(f1.y, v, acc[3]);
                acc[4] = fmaf(f2.x, v, acc[4]);
                acc[5] = fmaf(f2.y, v, acc[5]);
                acc[6] = fmaf(f3.x, v, acc[6]);
                acc[7] = fmaf(f3.y, v, acc[7]);
            }
        }
        __syncwarp();

        #pragma unroll
        for (int q = 0; q < 8; q++) {
            s->sp.sout[lane * 8 + q][w * 2 + cc] = acc[q];
        }
    }
    __syncthreads();

    // coalesced evict-first write: 64B per row segment out[b, j0..j0+15]
    int col = threadIdx.x & 15;
    int j   = ct * JT + col;
    if (j < N_GO) {
        #pragma unroll
        for (int r = threadIdx.x >> 4; r < BT; r += 16) {
            __stcs(&out[(size_t)(b0 + r) * N_GO + j], s->sp.sout[r][col]);
        }
    }
}

// ---------------------------------------------------------------------------
// Fused A: build entries (all) + transpose chunk 0 into buffer 0
__global__ void fused_build_transpose_kernel(const float* __restrict__ x,
                                             const float* __restrict__ w,
                                             const float* __restrict__ m) {
    __shared__ SmemU s;
    if (blockIdx.x < NB_BUILD) {
        build_role(w, m, blockIdx.x);
    } else {
        transpose_role(&s, x, 0, 0, blockIdx.x - NB_BUILD);
    }
}

// ---------------------------------------------------------------------------
// Fused B: spmm chunk c from buf (c&1) + (optionally) transpose chunk c+1
// into the other buffer. Kernel boundary orders transpose(c) before spmm(c).
__global__ void fused_spmm_transpose_kernel(float* __restrict__ out,
                                            const float* __restrict__ x,
                                            int chunk, int do_transpose) {
    __shared__ SmemU s;
    int buf = chunk & 1;
    if (blockIdx.x < NSP) {
        spmm_role(&s, out, chunk, buf, blockIdx.x);
    } else if (do_transpose) {
        transpose_role(&s, x, chunk + 1, buf ^ 1, blockIdx.x - NSP);
    }
}

// ---------------------------------------------------------------------------
// sort each column's entry list by gene id once (deterministic FP order),
// then write PAD duplicate zero-weight tail entries for the spmm prefetch.
__global__ void sort_entries_kernel() {
    __shared__ int   s_i[8][CAP];
    __shared__ float s_v[8][CAP];
    int w    = threadIdx.x >> 5;
    int lane = threadIdx.x & 31;
    int j    = blockIdx.x * 8 + w;
    if (j >= N_GO) return;
    int n = min(g_cnt[j], CAP);
    size_t base = (size_t)j * (CAP + PAD);

    for (int e = lane; e < n; e += 32) {
        s_i[w][e] = g_ei[base + e];
        s_v[w][e] = g_ev[base + e];
    }
    __syncwarp();
    for (int p = 0; p < n; p++) {
        for (int k = (p & 1) + 2 * lane; k + 1 < n; k += 64) {
            if (s_i[w][k] > s_i[w][k + 1]) {
                int   ti = s_i[w][k]; s_i[w][k] = s_i[w][k + 1]; s_i[w][k + 1] = ti;
                float tv = s_v[w][k]; s_v[w][k] = s_v[w][k + 1]; s_v[w][k + 1] = tv;
            }
        }
        __syncwarp();
    }
    for (int e = lane; e < n; e += 32) {
        g_ei[base + e] = s_i[w][e];
        g_ev[base + e] = s_v[w][e];
    }
    if (lane < PAD) {
        int last = (n > 0) ? s_i[w][n - 1] : 0;
        g_ei[base + n + lane] = last;
        g_ev[base + n + lane] = 0.f;
    }
}

// ---------------------------------------------------------------------------
extern "C" void kernel_launch(void* const* d_in, const int* in_sizes, int n_in,
                              void* d_out, int out_size) {
    const float* x = (const float*)d_in[0];   // [4096, 20000]
    const float* w = (const float*)d_in[1];   // [20000, 5000]
    const float* m = (const float*)d_in[2];   // [20000, 5000]
    float* out = (float*)d_out;               // [4096, 5000]

    // zero per-column counters via memset node (graph-capturable, no launch)
    void* cntp = nullptr;
    cudaGetSymbolAddress(&cntp, g_cnt);
    cudaMemsetAsync(cntp, 0, N_GO * sizeof(int));

    // A: build (all entries) + transpose chunk 0 into buf 0
    fused_build_transpose_kernel<<<NB_BUILD + NTR, 256>>>(x, w, m);

    sort_entries_kernel<<<(N_GO + 7) / 8, 256>>>();

    // B: spmm chunk c overlapped with transpose chunk c+1 (double-buffered)
    for (int c = 0; c < NCHUNK; c++) {
        int do_tr = (c + 1 < NCHUNK);
        int grid  = NSP + (do_tr ? NTR : 0);
        fused_spmm_transpose_kernel<<<grid, 256>>>(out, x, c, do_tr);
    }
}

// round 17
// speedup vs baseline: 1.4030x; 1.0089x over previous
#include <cuda_runtime.h>
#include <cuda_fp16.h>

// Problem constants (from reference)
#define K_GENES 20000
#define N_GO    5000
#define BATCH   4096
#define CAP     128            // per-column entry capacity (Poisson(16); max ~50)
#define PAD     4              // prefetch-depth padding entries
#define JT      16             // columns per spmm block
#define BT      128            // batch elems per spmm block (lane covers 4 halves)
#define CHUNK   512            // batch rows per chunk (staging 20MB x2 buffers, L2-resident)
#define NCHUNK  (BATCH / CHUNK)              // 8

#define CT      ((N_GO + JT - 1) / JT)       // 313 column tiles
#define NSP     (CT * (CHUNK / BT))          // 1252 spmm blocks per chunk
#define GT      313                          // gene tiles: ceil(20000/64)
#define NTR     (GT * (CHUNK / 64))          // 2504 transpose blocks per chunk
#define NB_BUILD 4736                        // build role blocks in fused kernel A

// Scratch in device globals. Double-buffered staging: [buf][gene][CHUNK] fp16.
__device__ __half g_stage[2 * (size_t)K_GENES * CHUNK];
__device__ int    g_cnt[N_GO];
__device__ int    g_ei [(size_t)N_GO * (CAP + PAD)]; // gene index per entry (padded)
__device__ float  g_ev [(size_t)N_GO * (CAP + PAD)]; // weight*mask value (padded)

// Shared-memory union: transpose tile OR spmm working set (never both in a block)
union SmemU {
    struct { float tile[64][65]; } tr;                 // 16.6 KB
    struct {
        int   ei[8][CAP + PAD];                        // 4.2 KB
        float ev[8][CAP + PAD];                        // 4.2 KB
        float sout[BT][JT + 1];                        // 8.7 KB
    } sp;                                              // 17.1 KB
};

// ---------------------------------------------------------------------------
// build role: scan mask (evict-first stream), append (gene, w*m) per column
__device__ __forceinline__ void build_role(const float* __restrict__ w,
                                           const float* __restrict__ m,
                                           int vblock) {
    const float4* m4 = (const float4*)m;
    const long total4 = (long)K_GENES * N_GO / 4;
    long stride = (long)NB_BUILD * 256;
    for (long idx = (long)vblock * 256 + threadIdx.x; idx < total4; idx += stride) {
        float4 mv = __ldcs(m4 + idx);
        if (mv.x != 0.f || mv.y != 0.f || mv.z != 0.f || mv.w != 0.f) {
            float lane[4] = {mv.x, mv.y, mv.z, mv.w};
            long base = idx * 4;
            #pragma unroll
            for (int c = 0; c < 4; c++) {
                if (lane[c] != 0.f) {
                    long lin = base + c;
                    int i = (int)(lin / N_GO);
                    int j = (int)(lin - (long)i * N_GO);
                    float wv = __ldg(w + lin) * lane[c];
                    int pos = atomicAdd(&g_cnt[j], 1);
                    if (pos < CAP) {
                        g_ei[(size_t)j * (CAP + PAD) + pos] = i;
                        g_ev[(size_t)j * (CAP + PAD) + pos] = wv;
                    }
                }
            }
        }
    }
}

// ---------------------------------------------------------------------------
// transpose role: one 64-gene x 64-batch tile of chunk -> staging buf
__device__ __forceinline__ void transpose_role(SmemU* s, const float* __restrict__ in,
                                               int chunk, int buf, int vblock) {
    __half* stg = g_stage + (size_t)buf * K_GENES * CHUNK;
    int t  = threadIdx.x;
    int c0 = (vblock % GT) * 64;             // gene base
    int rl = (vblock / GT) * 64;             // batch base within chunk
    int r0 = chunk * CHUNK + rl;             // global batch base

    int fx = t & 15;
    int rr = t >> 4;
    bool cok = (c0 + 4 * fx) < K_GENES;
    #pragma unroll
    for (int p = 0; p < 4; p++) {
        int r = rr + 16 * p;
        if (cok) {
            float4 v = __ldcs((const float4*)(in + (size_t)(r0 + r) * K_GENES + c0 + 4 * fx));
            s->tr.tile[r][4 * fx + 0] = v.x;
            s->tr.tile[r][4 * fx + 1] = v.y;
            s->tr.tile[r][4 * fx + 2] = v.z;
            s->tr.tile[r][4 * fx + 3] = v.w;
        }
    }
    __syncthreads();

    int u  = t & 7;
    int gl = t >> 3;
    #pragma unroll
    for (int p = 0; p < 2; p++) {
        int g = gl + 32 * p;
        if (c0 + g < K_GENES) {
            __half2 h0 = __floats2half2_rn(s->tr.tile[8 * u + 0][g], s->tr.tile[8 * u + 1][g]);
            __half2 h1 = __floats2half2_rn(s->tr.tile[8 * u + 2][g], s->tr.tile[8 * u + 3][g]);
            __half2 h2 = __floats2half2_rn(s->tr.tile[8 * u + 4][g], s->tr.tile[8 * u + 5][g]);
            __half2 h3 = __floats2half2_rn(s->tr.tile[8 * u + 6][g], s->tr.tile[8 * u + 7][g]);
            uint4 o;
            o.x = *(unsigned*)&h0; o.y = *(unsigned*)&h1;
            o.z = *(unsigned*)&h2; o.w = *(unsigned*)&h3;
            *(uint4*)&stg[(size_t)(c0 + g) * CHUNK + rl + 8 * u] = o;
        }
    }
}

// ---------------------------------------------------------------------------
// spmm role: (16 cols x 128 batch) tile of chunk from L2-resident staging.
// Warp w owns 2 columns. Lane covers 4 halves (uint2 loads). Depth-4
// LDG.64 prefetch -> MLP=4 with low reg pressure -> high occupancy too.
__device__ __forceinline__ void spmm_role(SmemU* s, float* __restrict__ out,
                                          int chunk, int buf, int vblock) {
    const __half* stg = g_stage + (size_t)buf * K_GENES * CHUNK;
    int ct    = vblock % CT;                 // column tile
    int bc    = vblock / CT;                 // batch sub-chunk
    int w     = threadIdx.x >> 5;
    int lane  = threadIdx.x & 31;
    int bl    = bc * BT;                     // batch base within chunk
    int b0    = chunk * CHUNK + bl;          // global batch base
    int jbase = ct * JT + w * 2;

    #pragma unroll
    for (int cc = 0; cc < 2; cc++) {
        int j = jbase + cc;
        int n = 0;
        if (j < N_GO) n = min(g_cnt[j], CAP);
        size_t lbase = (size_t)j * (CAP + PAD);

        for (int e = lane; e < n + PAD && j < N_GO; e += 32) {
            s->sp.ei[w][e] = g_ei[lbase + e];
            s->sp.ev[w][e] = g_ev[lbase + e];
        }
        __syncwarp();

        float acc[4];
        #pragma unroll
        for (int q = 0; q < 4; q++) acc[q] = 0.f;

        const __half* xb = stg + bl + lane * 4;
        if (n > 0) {
            uint2 u0 = __ldg((const uint2*)(xb + (size_t)s->sp.ei[w][0] * CHUNK));
            uint2 u1 = __ldg((const uint2*)(xb + (size_t)s->sp.ei[w][1] * CHUNK));
            uint2 u2 = __ldg((const uint2*)(xb + (size_t)s->sp.ei[w][2] * CHUNK));
            uint2 u3 = __ldg((const uint2*)(xb + (size_t)s->sp.ei[w][3] * CHUNK));
            for (int e = 0; e < n; e++) {
                uint2 cur = u0;
                u0 = u1; u1 = u2; u2 = u3;
                u3 = __ldg((const uint2*)(xb + (size_t)s->sp.ei[w][e + 4] * CHUNK));
                float v = s->sp.ev[w][e];
                float2 f0 = __half22float2(*(__half2*)&cur.x);
                float2 f1 = __half22float2(*(__half2*)&cur.y);
                acc[0] = fmaf(f0.x, v, acc[0]);
                acc[1] = fmaf(f0.y, v, acc[1]);
                acc[2] = fmaf(f1.x, v, acc[2]);
                acc[3] = fmaf(f1.y, v, acc[3]);
            }
        }
        __syncwarp();

        #pragma unroll
        for (int q = 0; q < 4; q++) {
            s->sp.sout[lane * 4 + q][w * 2 + cc] = acc[q];
        }
    }
    __syncthreads();

    // coalesced evict-first write: 64B per row segment out[b, j0..j0+15]
    int col = threadIdx.x & 15;
    int j   = ct * JT + col;
    if (j < N_GO) {
        #pragma unroll
        for (int r = threadIdx.x >> 4; r < BT; r += 16) {
            __stcs(&out[(size_t)(b0 + r) * N_GO + j], s->sp.sout[r][col]);
        }
    }
}

// ---------------------------------------------------------------------------
// Fused A: build entries (all) + transpose chunk 0 into buffer 0
__global__ void fused_build_transpose_kernel(const float* __restrict__ x,
                                             const float* __restrict__ w,
                                             const float* __restrict__ m) {
    __shared__ SmemU s;
    if (blockIdx.x < NB_BUILD) {
        build_role(w, m, blockIdx.x);
    } else {
        transpose_role(&s, x, 0, 0, blockIdx.x - NB_BUILD);
    }
}

// ---------------------------------------------------------------------------
// Fused B: spmm chunk c from buf (c&1) + (optionally) transpose chunk c+1
// into the other buffer. Kernel boundary orders transpose(c) before spmm(c).
__global__ void fused_spmm_transpose_kernel(float* __restrict__ out,
                                            const float* __restrict__ x,
                                            int chunk, int do_transpose) {
    __shared__ SmemU s;
    int buf = chunk & 1;
    if (blockIdx.x < NSP) {
        spmm_role(&s, out, chunk, buf, blockIdx.x);
    } else if (do_transpose) {
        transpose_role(&s, x, chunk + 1, buf ^ 1, blockIdx.x - NSP);
    }
}

// ---------------------------------------------------------------------------
// sort each column's entry list by gene id once (deterministic FP order),
// then write PAD duplicate zero-weight tail entries for the spmm prefetch.
__global__ void sort_entries_kernel() {
    __shared__ int   s_i[8][CAP];
    __shared__ float s_v[8][CAP];
    int w    = threadIdx.x >> 5;
    int lane = threadIdx.x & 31;
    int j    = blockIdx.x * 8 + w;
    if (j >= N_GO) return;
    int n = min(g_cnt[j], CAP);
    size_t base = (size_t)j * (CAP + PAD);

    for (int e = lane; e < n; e += 32) {
        s_i[w][e] = g_ei[base + e];
        s_v[w][e] = g_ev[base + e];
    }
    __syncwarp();
    for (int p = 0; p < n; p++) {
        for (int k = (p & 1) + 2 * lane; k + 1 < n; k += 64) {
            if (s_i[w][k] > s_i[w][k + 1]) {
                int   ti = s_i[w][k]; s_i[w][k] = s_i[w][k + 1]; s_i[w][k + 1] = ti;
                float tv = s_v[w][k]; s_v[w][k] = s_v[w][k + 1]; s_v[w][k + 1] = tv;
            }
        }
        __syncwarp();
    }
    for (int e = lane; e < n; e += 32) {
        g_ei[base + e] = s_i[w][e];
        g_ev[base + e] = s_v[w][e];
    }
    if (lane < PAD) {
        int last = (n > 0) ? s_i[w][n - 1] : 0;
        g_ei[base + n + lane] = last;
        g_ev[base + n + lane] = 0.f;
    }
}

// ---------------------------------------------------------------------------
extern "C" void kernel_launch(void* const* d_in, const int* in_sizes, int n_in,
                              void* d_out, int out_size) {
    const float* x = (const float*)d_in[0];   // [4096, 20000]
    const float* w = (const float*)d_in[1];   // [20000, 5000]
    const float* m = (const float*)d_in[2];   // [20000, 5000]
    float* out = (float*)d_out;               // [4096, 5000]

    // zero per-column counters via memset node (graph-capturable, no launch)
    void* cntp = nullptr;
    cudaGetSymbolAddress(&cntp, g_cnt);
    cudaMemsetAsync(cntp, 0, N_GO * sizeof(int));

    // A: build (all entries) + transpose chunk 0 into buf 0
    fused_build_transpose_kernel<<<NB_BUILD + NTR, 256>>>(x, w, m);

    sort_entries_kernel<<<(N_GO + 7) / 8, 256>>>();

    // B: spmm chunk c overlapped with transpose chunk c+1 (double-buffered)
    for (int c = 0; c < NCHUNK; c++) {
        int do_tr = (c + 1 < NCHUNK);
        int grid  = NSP + (do_tr ? NTR : 0);
        fused_spmm_transpose_kernel<<<grid, 256>>>(out, x, c, do_tr);
    }
}